// round 1
// baseline (speedup 1.0000x reference)
#include <cuda_runtime.h>
#include <cstdint>

// Problem constants
#define BATCH 4
#define DIN 128
#define HIN 192
#define WIN 192
#define KR  11
#define OH  182   // HIN - 10
#define OW  182   // WIN - 10
#define OD  118   // DIN - 10

#define MID_FIELD (BATCH * DIN * OH * OW)   // 16,959,488 per field
#define N_OUT 15634528.0                    // 4*118*182*182

// Gaussian(sigma=1.5, K=11), normalized. Matches reference to ~1e-7.
__constant__ float W11[11] = {
    0.00102834f, 0.00759875f, 0.03600077f, 0.10936078f, 0.21300553f,
    0.26601172f,
    0.21300553f, 0.10936078f, 0.03600077f, 0.00759875f, 0.00102834f
};

// Scratch: 5 fields x [B, D, OH, OW]  (~339 MB). Device global => allowed.
__device__ float g_mid[5ULL * MID_FIELD];
__device__ double g_acc;

__global__ void k_init() { g_acc = 0.0; }

// ---------------------------------------------------------------------------
// Kernel 1: per depth slice, fused 2D separable Gaussian over 5 fields.
// Tile: 16 x 32 outputs, halo 10 each dim.
// ---------------------------------------------------------------------------
#define TH 16
#define TW 32
#define RH (TH + 10)   // 26
#define RW (TW + 10)   // 42

__global__ __launch_bounds__(256)
void k_conv2d(const float* __restrict__ img1, const float* __restrict__ img2) {
    __shared__ float s1[RH][RW];
    __shared__ float s2[RH][RW];
    __shared__ float st[5][RH][TW];

    const int bz  = blockIdx.z;              // b*DIN + d
    const int oy0 = blockIdx.y * TH;
    const int ox0 = blockIdx.x * TW;
    const float* p1 = img1 + (size_t)bz * (HIN * WIN);
    const float* p2 = img2 + (size_t)bz * (HIN * WIN);

    const int tid = threadIdx.x;

    // Load input tiles (clamped; clamped values only feed guarded-off outputs)
    for (int i = tid; i < RH * RW; i += 256) {
        int r = i / RW, c = i - r * RW;
        int y = oy0 + r; if (y >= HIN) y = HIN - 1;
        int x = ox0 + c; if (x >= WIN) x = WIN - 1;
        int gi = y * WIN + x;
        s1[r][c] = p1[gi];
        s2[r][c] = p2[gi];
    }
    __syncthreads();

    // W pass: RH x TW points, products computed on the fly
    for (int i = tid; i < RH * TW; i += 256) {
        int r = i / TW, c = i - r * TW;
        float a0 = 0.f, b0 = 0.f, aa = 0.f, bb = 0.f, ab = 0.f;
#pragma unroll
        for (int k = 0; k < KR; k++) {
            float w = W11[k];
            float a = s1[r][c + k];
            float b = s2[r][c + k];
            float wa = w * a, wb = w * b;
            a0 += wa;
            b0 += wb;
            aa = fmaf(wa, a, aa);
            bb = fmaf(wb, b, bb);
            ab = fmaf(wa, b, ab);
        }
        st[0][r][c] = a0;
        st[1][r][c] = b0;
        st[2][r][c] = aa;
        st[3][r][c] = bb;
        st[4][r][c] = ab;
    }
    __syncthreads();

    // H pass: TH x TW outputs -> global intermediates
    for (int i = tid; i < TH * TW; i += 256) {
        int r = i / TW, c = i - r * TW;
        int oy = oy0 + r, ox = ox0 + c;
        if (oy < OH && ox < OW) {
            float acc0 = 0.f, acc1 = 0.f, acc2 = 0.f, acc3 = 0.f, acc4 = 0.f;
#pragma unroll
            for (int k = 0; k < KR; k++) {
                float w = W11[k];
                acc0 = fmaf(w, st[0][r + k][c], acc0);
                acc1 = fmaf(w, st[1][r + k][c], acc1);
                acc2 = fmaf(w, st[2][r + k][c], acc2);
                acc3 = fmaf(w, st[3][r + k][c], acc3);
                acc4 = fmaf(w, st[4][r + k][c], acc4);
            }
            size_t base = (size_t)bz * (OH * OW) + (size_t)oy * OW + ox;
            g_mid[0ULL * MID_FIELD + base] = acc0;
            g_mid[1ULL * MID_FIELD + base] = acc1;
            g_mid[2ULL * MID_FIELD + base] = acc2;
            g_mid[3ULL * MID_FIELD + base] = acc3;
            g_mid[4ULL * MID_FIELD + base] = acc4;
        }
    }
}

// ---------------------------------------------------------------------------
// Kernel 2: D-direction conv + SSIM map + reduction.
// One block per (b, y) output row. Ring buffer of 11 d-slices x 5 fields.
// Each intermediate element is read from DRAM exactly once.
// ---------------------------------------------------------------------------
__global__ __launch_bounds__(192)
void k_dconv_reduce() {
    __shared__ float ring[5][KR][192];
    __shared__ float wsum[6];

    const int by = blockIdx.x;          // b*OH + y
    const int b  = by / OH;
    const int y  = by - b * OH;
    const int w  = threadIdx.x;         // 0..191
    const bool act = (w < OW);
    const int wl = act ? w : 0;

    float partial = 0.f;

    for (int d = 0; d < DIN; d++) {
        int slot = d % KR;
        size_t idx = ((size_t)(b * DIN + d) * OH + y) * OW + wl;
#pragma unroll
        for (int f = 0; f < 5; f++)
            ring[f][slot][w] = g_mid[(size_t)f * MID_FIELD + idx];
        __syncthreads();

        if (d >= KR - 1) {
            int od = d - (KR - 1);
            int base = od % KR;
            float m1 = 0.f, m2 = 0.f, p11 = 0.f, p22 = 0.f, p12 = 0.f;
#pragma unroll
            for (int k = 0; k < KR; k++) {
                int s = base + k; if (s >= KR) s -= KR;
                float wt = W11[k];
                m1  = fmaf(wt, ring[0][s][w], m1);
                m2  = fmaf(wt, ring[1][s][w], m2);
                p11 = fmaf(wt, ring[2][s][w], p11);
                p22 = fmaf(wt, ring[3][s][w], p22);
                p12 = fmaf(wt, ring[4][s][w], p12);
            }
            float mu1s = m1 * m1;
            float mu2s = m2 * m2;
            float mu12 = m1 * m2;
            float sg1 = p11 - mu1s;
            float sg2 = p22 - mu2s;
            float sg12 = p12 - mu12;
            const float C1 = 1e-4f;       // (0.01*1.0)^2
            const float C2 = 9e-4f;       // (0.03*1.0)^2
            float num = (2.f * mu12 + C1) * (2.f * sg12 + C2);
            float den = (mu1s + mu2s + C1) * (sg1 + sg2 + C2);
            if (act) partial += num / den;
        }
        __syncthreads();   // protect ring slot overwritten next iteration
    }

    // Block reduction: warp shuffle -> 6 warp sums -> double atomic
    float v = act ? partial : 0.f;
#pragma unroll
    for (int o = 16; o > 0; o >>= 1)
        v += __shfl_down_sync(0xffffffffu, v, o);
    if ((threadIdx.x & 31) == 0) wsum[threadIdx.x >> 5] = v;
    __syncthreads();
    if (threadIdx.x == 0) {
        float s = 0.f;
#pragma unroll
        for (int i = 0; i < 6; i++) s += wsum[i];
        atomicAdd(&g_acc, (double)s);
    }
}

__global__ void k_finalize(float* __restrict__ out) {
    out[0] = (float)(g_acc / N_OUT);
}

extern "C" void kernel_launch(void* const* d_in, const int* in_sizes, int n_in,
                              void* d_out, int out_size) {
    const float* img1 = (const float*)d_in[0];
    const float* img2 = (const float*)d_in[1];
    float* out = (float*)d_out;

    k_init<<<1, 1>>>();

    dim3 g1((OW + TW - 1) / TW,      // 6
            (OH + TH - 1) / TH,      // 12
            BATCH * DIN);            // 512
    k_conv2d<<<g1, 256>>>(img1, img2);

    k_dconv_reduce<<<BATCH * OH, 192>>>();

    k_finalize<<<1, 1>>>(out);
}

// round 2
// speedup vs baseline: 1.1444x; 1.1444x over previous
#include <cuda_runtime.h>
#include <cstdint>

// Problem constants
#define BATCH 4
#define DIN   128
#define HIN   192
#define WIN   192
#define KR    11
#define OH    182     // HIN - 10
#define OW    182     // WIN - 10
#define OD    118     // DIN - 10
#define OWP   184     // padded intermediate row (32B-aligned rows)

#define DSTRIDE   (OH * OWP)                 // 33488 floats per (bz) slice
#define MIDF      (BATCH * DIN * DSTRIDE)    // 17,145,856 per field
#define N_OUT     15634528.0                 // 4*118*182*182

// Gaussian(sigma=1.5, K=11). constexpr + static indexing => FFMA-imm (rt 1).
__device__ constexpr float WG[11] = {
    0.00102834f, 0.00759875f, 0.03600077f, 0.10936078f, 0.21300553f,
    0.26601172f,
    0.21300553f, 0.10936078f, 0.03600077f, 0.00759875f, 0.00102834f
};

// Scratch: 5 fields x [B*D, OH, OWP]  (~343 MB). Device global => allowed.
__device__ float g_mid[5ULL * MIDF];
__device__ double g_acc;

__global__ void k_init() { g_acc = 0.0; }

// ---------------------------------------------------------------------------
// Kernel 1: per depth slice, fused separable 2D Gaussian over 5 fields.
// Output tile 16(y) x 32(x). Slab 26 x 42 (padded to 44).
// W-pass: 208 tasks, each 4 x-outputs from a 16-float register window.
// H-pass: 128 tasks, each 4 y-outputs streaming 14 taps.
// ---------------------------------------------------------------------------
#define TYO 16
#define TXO 32
#define SRH 26        // TYO + 10
#define SRW 44        // 42 padded to 44 (16B multiple)

__global__ __launch_bounds__(256)
void k_conv2d(const float* __restrict__ img1, const float* __restrict__ img2) {
    __shared__ float sa[SRH][SRW];
    __shared__ float sb[SRH][SRW];
    __shared__ float wt[5][SRH][TXO];   // W-pass result; x-stride 32 => conflict-free

    const int bz = blockIdx.z;                 // b*DIN + d
    const int y0 = blockIdx.y * TYO;
    const int x0 = blockIdx.x * TXO;
    const float* p1 = img1 + (size_t)bz * (HIN * WIN);
    const float* p2 = img2 + (size_t)bz * (HIN * WIN);
    const int tid = threadIdx.x;

    // ---- load slab: 2 fields x 26 rows x 11 float4 (covers 44 cols) ----
    for (int t = tid; t < 2 * SRH * 11; t += 256) {
        int fld = t / (SRH * 11);
        int s   = t - fld * (SRH * 11);
        int r   = s / 11, c = s - r * 11;
        int gy  = y0 + r;  if (gy > HIN - 1) gy = HIN - 1;
        int gx4 = x0 + c * 4;  if (gx4 > WIN - 4) gx4 = WIN - 4;   // keep 16B load in-bounds
        const float* src = fld ? p2 : p1;
        float4 v = *reinterpret_cast<const float4*>(src + gy * WIN + gx4);
        float (*dst)[SRW] = fld ? sb : sa;
        *reinterpret_cast<float4*>(&dst[r][c * 4]) = v;
    }
    __syncthreads();

    // ---- W pass: tasks = 26 rows x 8 segments, 4 outputs each ----
    if (tid < SRH * 8) {
        const int row = tid >> 3;
        const int xs  = (tid & 7) * 4;

        float a[16], b[16];
#pragma unroll
        for (int c = 0; c < 4; c++) {
            float4 va = *reinterpret_cast<const float4*>(&sa[row][xs + c * 4]);
            float4 vb = *reinterpret_cast<const float4*>(&sb[row][xs + c * 4]);
            a[c*4+0]=va.x; a[c*4+1]=va.y; a[c*4+2]=va.z; a[c*4+3]=va.w;
            b[c*4+0]=vb.x; b[c*4+1]=vb.y; b[c*4+2]=vb.z; b[c*4+3]=vb.w;
        }

        float m1[4] = {0,0,0,0}, m2[4] = {0,0,0,0};
        float q11[4] = {0,0,0,0}, q22[4] = {0,0,0,0}, q12[4] = {0,0,0,0};
#pragma unroll
        for (int p = 0; p < 14; p++) {
            float av = a[p], bv = b[p];
#pragma unroll
            for (int j = 0; j < 4; j++) {
                int k = p - j;
                if (k >= 0 && k <= 10) {
                    float w  = WG[k];          // immediate
                    float ta = w * av;
                    float tb = w * bv;
                    m1[j] += ta;
                    m2[j] += tb;
                    q11[j] = fmaf(ta, av, q11[j]);
                    q22[j] = fmaf(tb, bv, q22[j]);
                    q12[j] = fmaf(ta, bv, q12[j]);
                }
            }
        }
        *reinterpret_cast<float4*>(&wt[0][row][xs]) = make_float4(m1[0], m1[1], m1[2], m1[3]);
        *reinterpret_cast<float4*>(&wt[1][row][xs]) = make_float4(m2[0], m2[1], m2[2], m2[3]);
        *reinterpret_cast<float4*>(&wt[2][row][xs]) = make_float4(q11[0], q11[1], q11[2], q11[3]);
        *reinterpret_cast<float4*>(&wt[3][row][xs]) = make_float4(q22[0], q22[1], q22[2], q22[3]);
        *reinterpret_cast<float4*>(&wt[4][row][xs]) = make_float4(q12[0], q12[1], q12[2], q12[3]);
    }
    __syncthreads();

    // ---- H pass: tasks = 32 x-cols x 4 y-segments, 4 outputs each ----
    if (tid < TXO * 4) {
        const int x  = tid & 31;
        const int ys = (tid >> 5) * 4;

        float acc[5][4];
#pragma unroll
        for (int f = 0; f < 5; f++)
#pragma unroll
            for (int j = 0; j < 4; j++) acc[f][j] = 0.f;

#pragma unroll
        for (int q = 0; q < 14; q++) {
            float v0 = wt[0][ys + q][x];
            float v1 = wt[1][ys + q][x];
            float v2 = wt[2][ys + q][x];
            float v3 = wt[3][ys + q][x];
            float v4 = wt[4][ys + q][x];
#pragma unroll
            for (int j = 0; j < 4; j++) {
                int k = q - j;
                if (k >= 0 && k <= 10) {
                    acc[0][j] = fmaf(WG[k], v0, acc[0][j]);
                    acc[1][j] = fmaf(WG[k], v1, acc[1][j]);
                    acc[2][j] = fmaf(WG[k], v2, acc[2][j]);
                    acc[3][j] = fmaf(WG[k], v3, acc[3][j]);
                    acc[4][j] = fmaf(WG[k], v4, acc[4][j]);
                }
            }
        }

        const int ox = x0 + x;
        if (ox < OW) {
#pragma unroll
            for (int j = 0; j < 4; j++) {
                int oy = y0 + ys + j;
                if (oy < OH) {
                    size_t o = (size_t)bz * DSTRIDE + (size_t)oy * OWP + ox;
#pragma unroll
                    for (int f = 0; f < 5; f++)
                        g_mid[(size_t)f * MIDF + o] = acc[f][j];
                }
            }
        }
    }
}

// ---------------------------------------------------------------------------
// Kernel 2: D-direction conv + SSIM + reduction.
// One block per (b, y) row; each thread owns one w-column.
// 11-deep x 5-field history lives in REGISTERS (static indexing via
// unroll-by-11). No shared ring, no barriers in the main loop.
// ---------------------------------------------------------------------------
__global__ __launch_bounds__(192)
void k_dssim() {
    __shared__ float wsum[6];

    const int by = blockIdx.x;          // b*OH + y
    const int b  = by / OH;
    const int y  = by - b * OH;
    const int w  = threadIdx.x;         // 0..191
    const bool act = (w < OW);
    const int wl = act ? w : 0;

    const size_t base = ((size_t)(b * DIN) * OH + y) * OWP + wl;

    float h[5][11];
    float part = 0.f;

    for (int i0 = 0; i0 < 132; i0 += 11) {
#pragma unroll
        for (int r = 0; r < 11; r++) {
            const int d = i0 + r;
            if (d < DIN) {
                const size_t off = base + (size_t)d * DSTRIDE;
#pragma unroll
                for (int f = 0; f < 5; f++)
                    h[f][r] = g_mid[(size_t)f * MIDF + off];

                if (d >= 10) {
                    float m1 = 0.f, m2 = 0.f, p11 = 0.f, p22 = 0.f, p12 = 0.f;
#pragma unroll
                    for (int k = 0; k < 11; k++) {
                        const int s = (r + 1 + k) % 11;   // static after unroll
                        m1  = fmaf(WG[k], h[0][s], m1);
                        m2  = fmaf(WG[k], h[1][s], m2);
                        p11 = fmaf(WG[k], h[2][s], p11);
                        p22 = fmaf(WG[k], h[3][s], p22);
                        p12 = fmaf(WG[k], h[4][s], p12);
                    }
                    float mu1s = m1 * m1;
                    float mu2s = m2 * m2;
                    float mu12 = m1 * m2;
                    float sg1  = p11 - mu1s;
                    float sg2  = p22 - mu2s;
                    float sg12 = p12 - mu12;
                    const float C1 = 1e-4f;     // (0.01)^2
                    const float C2 = 9e-4f;     // (0.03)^2
                    float num = (2.f * mu12 + C1) * (2.f * sg12 + C2);
                    float den = (mu1s + mu2s + C1) * (sg1 + sg2 + C2);
                    if (act) part += num / den;
                }
            }
        }
    }

    // block reduction -> double atomic
    float v = part;
#pragma unroll
    for (int o = 16; o > 0; o >>= 1)
        v += __shfl_down_sync(0xffffffffu, v, o);
    if ((threadIdx.x & 31) == 0) wsum[threadIdx.x >> 5] = v;
    __syncthreads();
    if (threadIdx.x == 0) {
        float s = 0.f;
#pragma unroll
        for (int i = 0; i < 6; i++) s += wsum[i];
        atomicAdd(&g_acc, (double)s);
    }
}

__global__ void k_finalize(float* __restrict__ out) {
    out[0] = (float)(g_acc / N_OUT);
}

extern "C" void kernel_launch(void* const* d_in, const int* in_sizes, int n_in,
                              void* d_out, int out_size) {
    const float* img1 = (const float*)d_in[0];
    const float* img2 = (const float*)d_in[1];
    float* out = (float*)d_out;

    k_init<<<1, 1>>>();

    dim3 g1((OW + TXO - 1) / TXO,      // 6
            (OH + TYO - 1) / TYO,      // 12
            BATCH * DIN);              // 512
    k_conv2d<<<g1, 256>>>(img1, img2);

    k_dssim<<<BATCH * OH, 192>>>();

    k_finalize<<<1, 1>>>(out);
}